// round 5
// baseline (speedup 1.0000x reference)
#include <cuda_runtime.h>
#include <cuda_fp16.h>
#include <math.h>
#include <stdint.h>

// ---------------- problem constants ----------------
#define B_     2
#define C_     256
#define N_     32768
#define H_     128
#define W_     128
#define HW_    16384
#define NG_    3
#define DEPTH_ 4

// token split between tensor-core CM and FFMA CM (run concurrently)
#define NT_T   22528        // 352 tiles of 64  (tensor kernel)
#define NT_F   (N_ - NT_T)  // 10240 = 80 tiles of 128 (ffma kernel)

// ---------------- device scratch (static, no allocs) ----------------
__device__ float g_grid [B_*C_*HW_];   // scatter grid / conv input
__device__ float g_plane[B_*C_*HW_];   // conv output (rflat)
__device__ float g_skip [B_*C_*HW_];   // plane snapshot from depth 0 (grid 0)
__device__ float g_wpt  [B_*NG_*N_];
__device__ int   g_ci   [B_*NG_*N_];
__device__ float g_counts[B_*NG_*HW_];
__device__ float g_bnm[C_];
__device__ float g_bnr[C_];
__device__ float g_bn_sum[C_];
__device__ float g_bn_sq [C_];

// ---------------- mma helper (fp16 x fp16 -> fp32, m16n8k16) ----------------
__device__ __forceinline__ void mma_f16(float d[4], const uint32_t a[4], const uint32_t b[2]) {
    asm volatile(
        "mma.sync.aligned.m16n8k16.row.col.f32.f16.f16.f32 "
        "{%0,%1,%2,%3}, {%4,%5,%6,%7}, {%8,%9}, {%0,%1,%2,%3};\n"
        : "+f"(d[0]), "+f"(d[1]), "+f"(d[2]), "+f"(d[3])
        : "r"(a[0]), "r"(a[1]), "r"(a[2]), "r"(a[3]),
          "r"(b[0]), "r"(b[1]));
}

// ---------------- simple copies ----------------
__global__ void copy4_kernel(const float4* __restrict__ src, float4* __restrict__ dst, int n4) {
    int i = blockIdx.x * blockDim.x + threadIdx.x;
    if (i < n4) dst[i] = src[i];
}
__global__ void grid_init_kernel(int use_skip) {
    int i = blockIdx.x * blockDim.x + threadIdx.x;
    float4 v;
    if (use_skip) v = reinterpret_cast<const float4*>(g_skip)[i];
    else          v = make_float4(0.f, 0.f, 0.f, 0.f);
    reinterpret_cast<float4*>(g_grid)[i] = v;
    if (i < C_) { g_bn_sum[i] = 0.f; g_bn_sq[i] = 0.f; }
}

// ---------------- projection weights (once) ----------------
__global__ void zero_counts_kernel() {
    int i = blockIdx.x * blockDim.x + threadIdx.x;
    if (i < B_*NG_*HW_) g_counts[i] = 0.f;
}
__global__ void count_scatter_kernel(const int* __restrict__ cell_ind,
                                     const float* __restrict__ occ) {
    int i = blockIdx.x * blockDim.x + threadIdx.x;
    if (i >= B_*NG_*N_) return;
    int n = i % N_;
    int g = (i / N_) % NG_;
    int b = i / (NG_*N_);
    int ci = cell_ind[i];
    ci = min(max(ci, 0), HW_ - 1);
    g_ci[i] = ci;
    float o = occ[b*N_ + n];
    atomicAdd(&g_counts[(b*NG_ + g)*HW_ + ci], o*o);
}
__global__ void wpt_kernel(const float* __restrict__ occ) {
    int i = blockIdx.x * blockDim.x + threadIdx.x;
    if (i >= B_*NG_*N_) return;
    int n = i % N_;
    int g = (i / N_) % NG_;
    int b = i / (NG_*N_);
    float o = occ[b*N_ + n];
    float cnt = g_counts[(b*NG_ + g)*HW_ + g_ci[i]];
    g_wpt[i] = o / (o*cnt + 1e-6f);
}

// ---------------- SpatialMix: LN over channels + weighted scatter ----------------
__global__ void ln_scatter_kernel(const float* __restrict__ tokens,
                                  const float* __restrict__ lng,
                                  const float* __restrict__ lnb,
                                  int g) {
    __shared__ float sg[C_], sb[C_];
    int tid = threadIdx.x;
    sg[tid] = lng[tid];
    sb[tid] = lnb[tid];
    __syncthreads();

    int b = blockIdx.y;
    int n = blockIdx.x * 256 + tid;
    const float* tb = tokens + (size_t)b*C_*N_ + n;

    float s = 0.f, ss = 0.f;
    #pragma unroll 8
    for (int c = 0; c < C_; c++) {
        float x = tb[(size_t)c * N_];
        s += x; ss += x * x;
    }
    float m = s * (1.f / C_);
    float rstd = rsqrtf(ss * (1.f / C_) - m*m + 1e-5f);

    int   cell = g_ci [((size_t)b*NG_ + g)*N_ + n];
    float w    = g_wpt[((size_t)b*NG_ + g)*N_ + n];
    float* gb = g_grid + (size_t)b*C_*HW_ + cell;
    #pragma unroll 4
    for (int c = 0; c < C_; c++) {
        float x = tb[(size_t)c * N_];
        float v = ((x - m) * rstd * sg[c] + sb[c]) * w;
        atomicAdd(gb + (size_t)c * HW_, v);
    }
}

// ---------------- fused depthwise conv3x3 -> relu -> conv3x3 (+BN partial sums, +skip) ----------------
#define CONV_SMEM (2 * 130 * 132 * 4)
__global__ void dwconv2_kernel(const float* __restrict__ w1, const float* __restrict__ b1,
                               const float* __restrict__ w2, const float* __restrict__ b2,
                               int save_skip) {
    extern __shared__ float sm[];
    float* s0 = sm;
    float* s1 = sm + 130 * 132;

    int bc = blockIdx.x;
    int c  = bc % C_;
    const float* img = g_grid + (size_t)bc * HW_;
    float* out = g_plane + (size_t)bc * HW_;
    float* skp = g_skip  + (size_t)bc * HW_;

    for (int i = threadIdx.x; i < 130*132*2; i += blockDim.x) sm[i] = 0.f;
    __syncthreads();
    for (int i = threadIdx.x; i < HW_; i += blockDim.x) {
        int y = i >> 7, x = i & 127;
        s0[(y+1)*132 + (x+1)] = img[i];
    }
    float w[9];
    #pragma unroll
    for (int j = 0; j < 9; j++) w[j] = __ldg(w1 + c*9 + j);
    float bb = __ldg(b1 + c);
    __syncthreads();

    for (int i = threadIdx.x; i < HW_; i += blockDim.x) {
        int y = i >> 7, x = i & 127;
        const float* p = &s0[y*132 + x];
        float acc = bb;
        acc += w[0]*p[0]   + w[1]*p[1]   + w[2]*p[2];
        acc += w[3]*p[132] + w[4]*p[133] + w[5]*p[134];
        acc += w[6]*p[264] + w[7]*p[265] + w[8]*p[266];
        s1[(y+1)*132 + (x+1)] = fmaxf(acc, 0.f);
    }
    #pragma unroll
    for (int j = 0; j < 9; j++) w[j] = __ldg(w2 + c*9 + j);
    bb = __ldg(b2 + c);
    __syncthreads();

    float psum = 0.f, psq = 0.f;
    for (int i = threadIdx.x; i < HW_; i += blockDim.x) {
        int y = i >> 7, x = i & 127;
        const float* p = &s1[y*132 + x];
        float acc = bb;
        acc += w[0]*p[0]   + w[1]*p[1]   + w[2]*p[2];
        acc += w[3]*p[132] + w[4]*p[133] + w[5]*p[134];
        acc += w[6]*p[264] + w[7]*p[265] + w[8]*p[266];
        out[i] = acc;
        if (save_skip) skp[i] = acc;
        psum += acc;
        psq  += acc * acc;
    }
    // block-reduce BN partial sums into s0 (s0 no longer needed)
    __syncthreads();
    s0[threadIdx.x]       = psum;
    s0[256 + threadIdx.x] = psq;
    __syncthreads();
    for (int o = 128; o > 0; o >>= 1) {
        if (threadIdx.x < o) {
            s0[threadIdx.x]       += s0[threadIdx.x + o];
            s0[256 + threadIdx.x] += s0[256 + threadIdx.x + o];
        }
        __syncthreads();
    }
    if (threadIdx.x == 0) {
        atomicAdd(&g_bn_sum[c], s0[0]);
        atomicAdd(&g_bn_sq[c],  s0[256]);
    }
}

// ---------------- BN finalize (raw sums -> scaled mean/rstd) ----------------
__global__ void bn_final_kernel(const float* __restrict__ ascale) {
    int c = threadIdx.x;
    float s = __ldg(ascale + c);
    float m = g_bn_sum[c] * (1.f / (B_*HW_));
    float v = g_bn_sq[c]  * (1.f / (B_*HW_)) - m*m;
    g_bnm[c] = s * m;
    g_bnr[c] = rsqrtf(s*s*v + 1e-5f);
}

// ---------------- sigmoid gate + gather + residual add ----------------
__global__ void gather_update_kernel(float* __restrict__ tokens, int g,
                                     const float* __restrict__ ascale,
                                     const float* __restrict__ bng,
                                     const float* __restrict__ bnb) {
    int n = blockIdx.x * 256 + threadIdx.x;
    int c = blockIdx.y;
    int b = blockIdx.z;
    int cell = g_ci[((size_t)b*NG_ + g)*N_ + n];
    float p = g_plane[((size_t)b*C_ + c)*HW_ + cell];
    float y = p * __ldg(ascale + c);
    float t = (y - g_bnm[c]) * g_bnr[c] * __ldg(bng + c) + __ldg(bnb + c);
    float att = 1.f / (1.f + expf(-t));
    tokens[((size_t)b*C_ + c)*N_ + n] += att * p;
}

// ======================================================================
// ChannelMix kernel A: fp16 tensor-core (tokens [0, NT_T))
// ======================================================================
#define CM_NT        64
#define XS_STRIDE    132
#define WS_STRIDE    20
#define CM_SMEM_U32  (64*XS_STRIDE + 256*WS_STRIDE + 256 + 256 + 64 + 64 + 256 + 256)
#define CM_SMEM      (CM_SMEM_U32 * 4)

__device__ __forceinline__ void cm_gemm_f16(const float* __restrict__ Wg,
                                            const uint32_t* __restrict__ Xs,
                                            uint32_t* __restrict__ Ws,
                                            int tid, int gid, int tig, int wm, int wn,
                                            float acc[4][4][4]) {
    #pragma unroll
    for (int i = 0; i < 4; i++)
        #pragma unroll
        for (int j = 0; j < 4; j++)
            #pragma unroll
            for (int r = 0; r < 4; r++) acc[i][j][r] = 0.f;

    for (int k0 = 0; k0 < C_; k0 += 32) {
        const float4* wp = reinterpret_cast<const float4*>(Wg + (size_t)tid*C_ + k0);
        uint32_t pk[16];
        #pragma unroll
        for (int q = 0; q < 4; q++) {
            float4 u = wp[2*q], v = wp[2*q+1];
            __half2 h0 = __floats2half2_rn(u.x, u.y);
            __half2 h1 = __floats2half2_rn(u.z, u.w);
            __half2 h2 = __floats2half2_rn(v.x, v.y);
            __half2 h3 = __floats2half2_rn(v.z, v.w);
            pk[4*q+0] = *(uint32_t*)&h0;
            pk[4*q+1] = *(uint32_t*)&h1;
            pk[4*q+2] = *(uint32_t*)&h2;
            pk[4*q+3] = *(uint32_t*)&h3;
        }
        __syncthreads();
        uint4* wd = reinterpret_cast<uint4*>(Ws + tid*WS_STRIDE);
        wd[0] = make_uint4(pk[0],  pk[1],  pk[2],  pk[3]);
        wd[1] = make_uint4(pk[4],  pk[5],  pk[6],  pk[7]);
        wd[2] = make_uint4(pk[8],  pk[9],  pk[10], pk[11]);
        wd[3] = make_uint4(pk[12], pk[13], pk[14], pk[15]);
        __syncthreads();

        #pragma unroll
        for (int kk = 0; kk < 2; kk++) {
            uint32_t bfr[4][2];
            #pragma unroll
            for (int j = 0; j < 4; j++) {
                const uint32_t* xr = Xs + (wn + j*8 + gid)*XS_STRIDE + (k0 >> 1) + kk*8;
                bfr[j][0] = xr[tig];
                bfr[j][1] = xr[tig + 4];
            }
            #pragma unroll
            for (int i = 0; i < 4; i++) {
                const uint32_t* w0 = Ws + (wm + i*16 + gid)*WS_STRIDE + kk*8;
                const uint32_t* w1 = w0 + 8*WS_STRIDE;
                uint32_t afr[4];
                afr[0] = w0[tig];
                afr[1] = w1[tig];
                afr[2] = w0[tig + 4];
                afr[3] = w1[tig + 4];
                #pragma unroll
                for (int j = 0; j < 4; j++)
                    mma_f16(acc[i][j], afr, bfr[j]);
            }
        }
    }
}

__global__ void __launch_bounds__(256, 2)
channelmix_tc_kernel(float* __restrict__ tokens,
                     const float* __restrict__ lng, const float* __restrict__ lnb,
                     const float* __restrict__ W1,  const float* __restrict__ b1,
                     const float* __restrict__ W2,  const float* __restrict__ b2,
                     const float* __restrict__ csc) {
    extern __shared__ uint32_t smu[];
    uint32_t* Xs    = smu;
    uint32_t* Ws    = Xs + 64*XS_STRIDE;
    float* red      = (float*)(Ws + 256*WS_STRIDE);
    float* red2     = red + 256;
    float* mean_s   = red2 + 256;
    float* rstd_s   = mean_s + 64;
    float* lg       = rstd_s + 64;
    float* lb       = lg + 256;
    __half* Xh      = reinterpret_cast<__half*>(Xs);

    const int tid  = threadIdx.x;
    const int b    = blockIdx.y;
    const int n0   = blockIdx.x * CM_NT;
    const int lane = tid & 31;
    const int wid  = tid >> 5;
    const int gid  = lane >> 2;
    const int tig  = lane & 3;
    const int wm   = (wid >> 1) * 64;
    const int wn   = (wid & 1)  * 32;

    lg[tid] = lng[tid];
    lb[tid] = lnb[tid];

    const int part = tid >> 6;
    const int nn   = tid & 63;
    const float* tcol = tokens + (size_t)b*C_*N_ + n0 + nn;
    float s = 0.f, ss = 0.f;
    #pragma unroll 8
    for (int c = part*64; c < part*64 + 64; c++) {
        float x = tcol[(size_t)c * N_];
        s += x; ss += x*x;
    }
    red [part*64 + nn] = s;
    red2[part*64 + nn] = ss;
    __syncthreads();
    if (tid < 64) {
        float sm  = red [tid] + red [64+tid] + red [128+tid] + red [192+tid];
        float sm2 = red2[tid] + red2[64+tid] + red2[128+tid] + red2[192+tid];
        float m = sm * (1.f / C_);
        mean_s[tid] = m;
        rstd_s[tid] = rsqrtf(sm2 * (1.f / C_) - m*m + 1e-5f);
    }
    __syncthreads();
    {
        float m = mean_s[nn], r = rstd_s[nn];
        #pragma unroll 8
        for (int c = part*64; c < part*64 + 64; c++) {
            float x = tcol[(size_t)c * N_];
            Xh[nn*(2*XS_STRIDE) + c] = __float2half((x - m) * r * lg[c] + lb[c]);
        }
    }

    float acc[4][4][4];

    cm_gemm_f16(W1, Xs, Ws, tid, gid, tig, wm, wn, acc);

    __syncthreads();
    #pragma unroll
    for (int i = 0; i < 4; i++) {
        int m0 = wm + i*16 + gid;
        float bva = __ldg(b1 + m0);
        float bvb = __ldg(b1 + m0 + 8);
        #pragma unroll
        for (int j = 0; j < 4; j++) {
            int col = wn + j*8 + 2*tig;
            Xh[ col   *(2*XS_STRIDE) + m0    ] = __float2half(fmaxf(acc[i][j][0] + bva, 0.f));
            Xh[(col+1)*(2*XS_STRIDE) + m0    ] = __float2half(fmaxf(acc[i][j][1] + bva, 0.f));
            Xh[ col   *(2*XS_STRIDE) + m0 + 8] = __float2half(fmaxf(acc[i][j][2] + bvb, 0.f));
            Xh[(col+1)*(2*XS_STRIDE) + m0 + 8] = __float2half(fmaxf(acc[i][j][3] + bvb, 0.f));
        }
    }

    cm_gemm_f16(W2, Xs, Ws, tid, gid, tig, wm, wn, acc);

    #pragma unroll
    for (int i = 0; i < 4; i++) {
        int m0 = wm + i*16 + gid;
        float b2a = __ldg(b2 + m0),     sca = __ldg(csc + m0);
        float b2b = __ldg(b2 + m0 + 8), scb = __ldg(csc + m0 + 8);
        #pragma unroll
        for (int j = 0; j < 4; j++) {
            int col = wn + j*8 + 2*tig;
            float* p0 = tokens + ((size_t)b*C_ + m0    )*N_ + n0 + col;
            float* p1 = tokens + ((size_t)b*C_ + m0 + 8)*N_ + n0 + col;
            float2 t0 = *reinterpret_cast<float2*>(p0);
            float2 t1 = *reinterpret_cast<float2*>(p1);
            t0.x += (acc[i][j][0] + b2a) * sca;
            t0.y += (acc[i][j][1] + b2a) * sca;
            t1.x += (acc[i][j][2] + b2b) * scb;
            t1.y += (acc[i][j][3] + b2b) * scb;
            *reinterpret_cast<float2*>(p0) = t0;
            *reinterpret_cast<float2*>(p1) = t1;
        }
    }
}

// ======================================================================
// ChannelMix kernel B: fp32 FFMA (tokens [NT_T, N_)), from R0 (exact)
// ======================================================================
#define CF_NT 128
#define CF_WS 258
#define CF_SMEM ((C_*CF_NT + 16*CF_WS + 512 + 512 + 128 + 128 + 256 + 256) * 4)

__global__ void __launch_bounds__(512, 1)
channelmix_ffma_kernel(float* __restrict__ tokens,
                       const float* __restrict__ lng, const float* __restrict__ lnb,
                       const float* __restrict__ W1,  const float* __restrict__ b1,
                       const float* __restrict__ W2,  const float* __restrict__ b2,
                       const float* __restrict__ csc) {
    extern __shared__ float smf[];
    float* Xs     = smf;                       // [256][128]
    float* Ws     = Xs + C_*CF_NT;             // [16][258]
    float* red    = Ws + 16*CF_WS;             // [4][128]
    float* red2   = red + 512;
    float* mean_s = red2 + 512;
    float* rstd_s = mean_s + 128;
    float* lg     = rstd_s + 128;
    float* lb     = lg + 256;

    const int tid = threadIdx.x;
    const int b   = blockIdx.y;
    const int n0  = NT_T + blockIdx.x * CF_NT;

    for (int i = tid; i < (C_*CF_NT)/4; i += 512) {
        int k  = i >> 5;
        int nv = i & 31;
        float4 v = *reinterpret_cast<const float4*>(tokens + ((size_t)b*C_ + k)*N_ + n0 + nv*4);
        reinterpret_cast<float4*>(Xs)[(k << 5) + nv] = v;
    }
    if (tid < 256) { lg[tid] = lng[tid]; lb[tid] = lnb[tid]; }
    __syncthreads();

    {
        int col = tid & 127, part = tid >> 7;
        float s = 0.f, ss = 0.f;
        int k0 = part * 64;
        #pragma unroll 4
        for (int k = k0; k < k0 + 64; k++) {
            float x = Xs[k*CF_NT + col];
            s += x; ss += x*x;
        }
        red [part*128 + col] = s;
        red2[part*128 + col] = ss;
    }
    __syncthreads();
    if (tid < 128) {
        float s  = red [tid] + red [128+tid] + red [256+tid] + red [384+tid];
        float ss = red2[tid] + red2[128+tid] + red2[256+tid] + red2[384+tid];
        float m = s * (1.f / C_);
        float v = ss * (1.f / C_) - m*m;
        mean_s[tid] = m;
        rstd_s[tid] = rsqrtf(v + 1e-5f);
    }
    __syncthreads();
    for (int i = tid; i < C_*CF_NT; i += 512) {
        int k = i >> 7, col = i & 127;
        Xs[i] = (Xs[i] - mean_s[col]) * rstd_s[col] * lg[k] + lb[k];
    }
    __syncthreads();

    const int tx = tid & 15;
    const int ty = tid >> 4;
    float acc[8][8];

    // ===== GEMM 1 =====
    #pragma unroll
    for (int i = 0; i < 8; i++)
        #pragma unroll
        for (int j = 0; j < 8; j++) acc[i][j] = 0.f;

    for (int k0 = 0; k0 < C_; k0 += 16) {
        {
            int m   = tid >> 1;
            int kk0 = (tid & 1) << 3;
            const float4* wr = reinterpret_cast<const float4*>(W1 + m*C_ + k0 + kk0);
            float4 a = wr[0], c4 = wr[1];
            Ws[(kk0+0)*CF_WS + m] = a.x;  Ws[(kk0+1)*CF_WS + m] = a.y;
            Ws[(kk0+2)*CF_WS + m] = a.z;  Ws[(kk0+3)*CF_WS + m] = a.w;
            Ws[(kk0+4)*CF_WS + m] = c4.x; Ws[(kk0+5)*CF_WS + m] = c4.y;
            Ws[(kk0+6)*CF_WS + m] = c4.z; Ws[(kk0+7)*CF_WS + m] = c4.w;
        }
        __syncthreads();
        #pragma unroll
        for (int kk = 0; kk < 16; kk++) {
            float xf[8], wf[8];
            float4 x0 = *reinterpret_cast<float4*>(&Xs[(k0+kk)*CF_NT + tx*8]);
            float4 x1 = *reinterpret_cast<float4*>(&Xs[(k0+kk)*CF_NT + tx*8 + 4]);
            xf[0]=x0.x; xf[1]=x0.y; xf[2]=x0.z; xf[3]=x0.w;
            xf[4]=x1.x; xf[5]=x1.y; xf[6]=x1.z; xf[7]=x1.w;
            #pragma unroll
            for (int i = 0; i < 8; i++) wf[i] = Ws[kk*CF_WS + ty*8 + i];
            #pragma unroll
            for (int i = 0; i < 8; i++)
                #pragma unroll
                for (int j = 0; j < 8; j++)
                    acc[i][j] = fmaf(wf[i], xf[j], acc[i][j]);
        }
        __syncthreads();
    }

    #pragma unroll
    for (int i = 0; i < 8; i++) {
        int m = ty*8 + i;
        float bv = __ldg(b1 + m);
        float4 v0, v1;
        v0.x = fmaxf(acc[i][0]+bv, 0.f); v0.y = fmaxf(acc[i][1]+bv, 0.f);
        v0.z = fmaxf(acc[i][2]+bv, 0.f); v0.w = fmaxf(acc[i][3]+bv, 0.f);
        v1.x = fmaxf(acc[i][4]+bv, 0.f); v1.y = fmaxf(acc[i][5]+bv, 0.f);
        v1.z = fmaxf(acc[i][6]+bv, 0.f); v1.w = fmaxf(acc[i][7]+bv, 0.f);
        *reinterpret_cast<float4*>(&Xs[m*CF_NT + tx*8])     = v0;
        *reinterpret_cast<float4*>(&Xs[m*CF_NT + tx*8 + 4]) = v1;
    }
    __syncthreads();

    // ===== GEMM 2 =====
    #pragma unroll
    for (int i = 0; i < 8; i++)
        #pragma unroll
        for (int j = 0; j < 8; j++) acc[i][j] = 0.f;

    for (int k0 = 0; k0 < C_; k0 += 16) {
        {
            int m   = tid >> 1;
            int kk0 = (tid & 1) << 3;
            const float4* wr = reinterpret_cast<const float4*>(W2 + m*C_ + k0 + kk0);
            float4 a = wr[0], c4 = wr[1];
            Ws[(kk0+0)*CF_WS + m] = a.x;  Ws[(kk0+1)*CF_WS + m] = a.y;
            Ws[(kk0+2)*CF_WS + m] = a.z;  Ws[(kk0+3)*CF_WS + m] = a.w;
            Ws[(kk0+4)*CF_WS + m] = c4.x; Ws[(kk0+5)*CF_WS + m] = c4.y;
            Ws[(kk0+6)*CF_WS + m] = c4.z; Ws[(kk0+7)*CF_WS + m] = c4.w;
        }
        __syncthreads();
        #pragma unroll
        for (int kk = 0; kk < 16; kk++) {
            float xf[8], wf[8];
            float4 x0 = *reinterpret_cast<float4*>(&Xs[(k0+kk)*CF_NT + tx*8]);
            float4 x1 = *reinterpret_cast<float4*>(&Xs[(k0+kk)*CF_NT + tx*8 + 4]);
            xf[0]=x0.x; xf[1]=x0.y; xf[2]=x0.z; xf[3]=x0.w;
            xf[4]=x1.x; xf[5]=x1.y; xf[6]=x1.z; xf[7]=x1.w;
            #pragma unroll
            for (int i = 0; i < 8; i++) wf[i] = Ws[kk*CF_WS + ty*8 + i];
            #pragma unroll
            for (int i = 0; i < 8; i++)
                #pragma unroll
                for (int j = 0; j < 8; j++)
                    acc[i][j] = fmaf(wf[i], xf[j], acc[i][j]);
        }
        __syncthreads();
    }

    #pragma unroll
    for (int i = 0; i < 8; i++) {
        int m = ty*8 + i;
        float bv = __ldg(b2 + m);
        float sc = __ldg(csc + m);
        float* trow = tokens + ((size_t)b*C_ + m)*N_ + n0 + tx*8;
        float4 t0 = *reinterpret_cast<float4*>(trow);
        float4 t1 = *reinterpret_cast<float4*>(trow + 4);
        t0.x += (acc[i][0]+bv)*sc; t0.y += (acc[i][1]+bv)*sc;
        t0.z += (acc[i][2]+bv)*sc; t0.w += (acc[i][3]+bv)*sc;
        t1.x += (acc[i][4]+bv)*sc; t1.y += (acc[i][5]+bv)*sc;
        t1.z += (acc[i][6]+bv)*sc; t1.w += (acc[i][7]+bv)*sc;
        *reinterpret_cast<float4*>(trow)     = t0;
        *reinterpret_cast<float4*>(trow + 4) = t1;
    }
}

// ---------------- launch ----------------
extern "C" void kernel_launch(void* const* d_in, const int* in_sizes, int n_in,
                              void* d_out, int out_size) {
    const float* tokens_in  = (const float*)d_in[0];
    const int*   cell_ind   = (const int*)  d_in[1];
    const float* occ        = (const float*)d_in[2];
    const float* smix_ln_g  = (const float*)d_in[3];
    const float* smix_ln_b  = (const float*)d_in[4];
    const float* ffn_w1     = (const float*)d_in[5];
    const float* ffn_b1     = (const float*)d_in[6];
    const float* ffn_w2     = (const float*)d_in[7];
    const float* ffn_b2     = (const float*)d_in[8];
    const float* att_scale  = (const float*)d_in[9];
    const float* att_bn_g   = (const float*)d_in[10];
    const float* att_bn_b   = (const float*)d_in[11];
    const float* cmix_ln_g  = (const float*)d_in[12];
    const float* cmix_ln_b  = (const float*)d_in[13];
    const float* cmix_w1    = (const float*)d_in[14];
    const float* cmix_b1    = (const float*)d_in[15];
    const float* cmix_w2    = (const float*)d_in[16];
    const float* cmix_b2    = (const float*)d_in[17];
    const float* cmix_scale = (const float*)d_in[18];
    float* tokens = (float*)d_out;

    cudaFuncSetAttribute(dwconv2_kernel,         cudaFuncAttributeMaxDynamicSharedMemorySize, CONV_SMEM);
    cudaFuncSetAttribute(channelmix_tc_kernel,   cudaFuncAttributeMaxDynamicSharedMemorySize, CM_SMEM);
    cudaFuncSetAttribute(channelmix_ffma_kernel, cudaFuncAttributeMaxDynamicSharedMemorySize, CF_SMEM);

    // side stream + events for the CM fork-join (created/destroyed per call;
    // host-side objects only, no device allocations)
    cudaStream_t s2;
    cudaStreamCreateWithFlags(&s2, cudaStreamNonBlocking);
    cudaEvent_t evFork, evJoin;
    cudaEventCreateWithFlags(&evFork, cudaEventDisableTiming);
    cudaEventCreateWithFlags(&evJoin, cudaEventDisableTiming);

    copy4_kernel<<<(B_*C_*N_/4 + 255)/256, 256>>>(
        reinterpret_cast<const float4*>(tokens_in),
        reinterpret_cast<float4*>(tokens), B_*C_*N_/4);

    zero_counts_kernel <<<(B_*NG_*HW_ + 255)/256, 256>>>();
    count_scatter_kernel<<<(B_*NG_*N_ + 255)/256, 256>>>(cell_ind, occ);
    wpt_kernel          <<<(B_*NG_*N_ + 255)/256, 256>>>(occ);

    for (int d = 0; d < DEPTH_; d++) {
        int g = d % NG_;
        grid_init_kernel<<<(B_*C_*HW_/4)/256, 256>>>((d == 3 && g == 0) ? 1 : 0);

        ln_scatter_kernel<<<dim3(N_/256, B_), 256>>>(tokens, smix_ln_g + d*C_, smix_ln_b + d*C_, g);

        dwconv2_kernel<<<B_*C_, 256, CONV_SMEM>>>(ffn_w1 + d*C_*9, ffn_b1 + d*C_,
                                                  ffn_w2 + d*C_*9, ffn_b2 + d*C_,
                                                  (d == 0) ? 1 : 0);

        bn_final_kernel<<<1, C_>>>(att_scale + d*C_);

        gather_update_kernel<<<dim3(N_/256, C_, B_), 256>>>(tokens, g,
                                                            att_scale + d*C_,
                                                            att_bn_g + d*C_,
                                                            att_bn_b + d*C_);

        // ---- ChannelMix: tensor-core branch + FFMA branch, concurrent ----
        cudaEventRecord(evFork, 0);
        cudaStreamWaitEvent(s2, evFork, 0);

        channelmix_tc_kernel<<<dim3(NT_T/CM_NT, B_), 256, CM_SMEM>>>(
            tokens,
            cmix_ln_g + d*C_, cmix_ln_b + d*C_,
            cmix_w1 + d*C_*C_, cmix_b1 + d*C_,
            cmix_w2 + d*C_*C_, cmix_b2 + d*C_,
            cmix_scale + d*C_);

        channelmix_ffma_kernel<<<dim3(NT_F/CF_NT, B_), 512, CF_SMEM, s2>>>(
            tokens,
            cmix_ln_g + d*C_, cmix_ln_b + d*C_,
            cmix_w1 + d*C_*C_, cmix_b1 + d*C_,
            cmix_w2 + d*C_*C_, cmix_b2 + d*C_,
            cmix_scale + d*C_);

        cudaEventRecord(evJoin, s2);
        cudaStreamWaitEvent(0, evJoin, 0);
    }

    cudaEventDestroy(evFork);
    cudaEventDestroy(evJoin);
    cudaStreamDestroy(s2);
}

// round 6
// speedup vs baseline: 1.4325x; 1.4325x over previous
#include <cuda_runtime.h>
#include <cuda_fp16.h>
#include <math.h>
#include <stdint.h>

// ---------------- problem constants ----------------
#define B_     2
#define C_     256
#define N_     32768
#define H_     128
#define W_     128
#define HW_    16384
#define NG_    3
#define DEPTH_ 4

// ---------------- device scratch (static, no allocs) ----------------
__device__ float g_grid [B_*C_*HW_];   // scatter grid / conv input
__device__ float g_plane[B_*C_*HW_];   // conv output (rflat)
__device__ float g_skip [B_*C_*HW_];   // plane snapshot from depth 0 (grid 0)
__device__ float g_wpt  [B_*NG_*N_];
__device__ int   g_ci   [B_*NG_*N_];
__device__ float g_counts[B_*NG_*HW_];
__device__ float g_bnm[C_];
__device__ float g_bnr[C_];
__device__ float g_bn_sum[C_];
__device__ float g_bn_sq [C_];
__device__ __half g_h[(size_t)B_*N_*C_];   // relu(h1), fp16, token-major [b][n][k]

// ---------------- mma helper (fp16 x fp16 -> fp32, m16n8k16) ----------------
__device__ __forceinline__ void mma_f16(float d[4], const uint32_t a[4], const uint32_t b[2]) {
    asm volatile(
        "mma.sync.aligned.m16n8k16.row.col.f32.f16.f16.f32 "
        "{%0,%1,%2,%3}, {%4,%5,%6,%7}, {%8,%9}, {%0,%1,%2,%3};\n"
        : "+f"(d[0]), "+f"(d[1]), "+f"(d[2]), "+f"(d[3])
        : "r"(a[0]), "r"(a[1]), "r"(a[2]), "r"(a[3]),
          "r"(b[0]), "r"(b[1]));
}

// ---------------- simple copies ----------------
__global__ void copy4_kernel(const float4* __restrict__ src, float4* __restrict__ dst, int n4) {
    int i = blockIdx.x * blockDim.x + threadIdx.x;
    if (i < n4) dst[i] = src[i];
}
__global__ void grid_init_kernel(int use_skip) {
    int i = blockIdx.x * blockDim.x + threadIdx.x;
    float4 v;
    if (use_skip) v = reinterpret_cast<const float4*>(g_skip)[i];
    else          v = make_float4(0.f, 0.f, 0.f, 0.f);
    reinterpret_cast<float4*>(g_grid)[i] = v;
    if (i < C_) { g_bn_sum[i] = 0.f; g_bn_sq[i] = 0.f; }
}

// ---------------- projection weights (once) ----------------
__global__ void zero_counts_kernel() {
    int i = blockIdx.x * blockDim.x + threadIdx.x;
    if (i < B_*NG_*HW_) g_counts[i] = 0.f;
}
__global__ void count_scatter_kernel(const int* __restrict__ cell_ind,
                                     const float* __restrict__ occ) {
    int i = blockIdx.x * blockDim.x + threadIdx.x;
    if (i >= B_*NG_*N_) return;
    int n = i % N_;
    int g = (i / N_) % NG_;
    int b = i / (NG_*N_);
    int ci = cell_ind[i];
    ci = min(max(ci, 0), HW_ - 1);
    g_ci[i] = ci;
    float o = occ[b*N_ + n];
    atomicAdd(&g_counts[(b*NG_ + g)*HW_ + ci], o*o);
}
__global__ void wpt_kernel(const float* __restrict__ occ) {
    int i = blockIdx.x * blockDim.x + threadIdx.x;
    if (i >= B_*NG_*N_) return;
    int n = i % N_;
    int g = (i / N_) % NG_;
    int b = i / (NG_*N_);
    float o = occ[b*N_ + n];
    float cnt = g_counts[(b*NG_ + g)*HW_ + g_ci[i]];
    g_wpt[i] = o / (o*cnt + 1e-6f);
}

// ---------------- SpatialMix: LN over channels + weighted scatter ----------------
__global__ void ln_scatter_kernel(const float* __restrict__ tokens,
                                  const float* __restrict__ lng,
                                  const float* __restrict__ lnb,
                                  int g) {
    __shared__ float sg[C_], sb[C_];
    int tid = threadIdx.x;
    sg[tid] = lng[tid];
    sb[tid] = lnb[tid];
    __syncthreads();

    int b = blockIdx.y;
    int n = blockIdx.x * 256 + tid;
    const float* tb = tokens + (size_t)b*C_*N_ + n;

    float s = 0.f, ss = 0.f;
    #pragma unroll 8
    for (int c = 0; c < C_; c++) {
        float x = tb[(size_t)c * N_];
        s += x; ss += x * x;
    }
    float m = s * (1.f / C_);
    float rstd = rsqrtf(ss * (1.f / C_) - m*m + 1e-5f);

    int   cell = g_ci [((size_t)b*NG_ + g)*N_ + n];
    float w    = g_wpt[((size_t)b*NG_ + g)*N_ + n];
    float* gb = g_grid + (size_t)b*C_*HW_ + cell;
    #pragma unroll 4
    for (int c = 0; c < C_; c++) {
        float x = tb[(size_t)c * N_];
        float v = ((x - m) * rstd * sg[c] + sb[c]) * w;
        atomicAdd(gb + (size_t)c * HW_, v);
    }
}

// ---------------- fused depthwise conv3x3 -> relu -> conv3x3 (+BN sums, +skip) ----------------
#define CONV_SMEM (2 * 130 * 132 * 4)
__global__ void dwconv2_kernel(const float* __restrict__ w1, const float* __restrict__ b1,
                               const float* __restrict__ w2, const float* __restrict__ b2,
                               int save_skip) {
    extern __shared__ float sm[];
    float* s0 = sm;
    float* s1 = sm + 130 * 132;

    int bc = blockIdx.x;
    int c  = bc % C_;
    const float* img = g_grid + (size_t)bc * HW_;
    float* out = g_plane + (size_t)bc * HW_;
    float* skp = g_skip  + (size_t)bc * HW_;

    for (int i = threadIdx.x; i < 130*132*2; i += blockDim.x) sm[i] = 0.f;
    __syncthreads();
    for (int i = threadIdx.x; i < HW_; i += blockDim.x) {
        int y = i >> 7, x = i & 127;
        s0[(y+1)*132 + (x+1)] = img[i];
    }
    float w[9];
    #pragma unroll
    for (int j = 0; j < 9; j++) w[j] = __ldg(w1 + c*9 + j);
    float bb = __ldg(b1 + c);
    __syncthreads();

    for (int i = threadIdx.x; i < HW_; i += blockDim.x) {
        int y = i >> 7, x = i & 127;
        const float* p = &s0[y*132 + x];
        float acc = bb;
        acc += w[0]*p[0]   + w[1]*p[1]   + w[2]*p[2];
        acc += w[3]*p[132] + w[4]*p[133] + w[5]*p[134];
        acc += w[6]*p[264] + w[7]*p[265] + w[8]*p[266];
        s1[(y+1)*132 + (x+1)] = fmaxf(acc, 0.f);
    }
    #pragma unroll
    for (int j = 0; j < 9; j++) w[j] = __ldg(w2 + c*9 + j);
    bb = __ldg(b2 + c);
    __syncthreads();

    float psum = 0.f, psq = 0.f;
    for (int i = threadIdx.x; i < HW_; i += blockDim.x) {
        int y = i >> 7, x = i & 127;
        const float* p = &s1[y*132 + x];
        float acc = bb;
        acc += w[0]*p[0]   + w[1]*p[1]   + w[2]*p[2];
        acc += w[3]*p[132] + w[4]*p[133] + w[5]*p[134];
        acc += w[6]*p[264] + w[7]*p[265] + w[8]*p[266];
        out[i] = acc;
        if (save_skip) skp[i] = acc;
        psum += acc;
        psq  += acc * acc;
    }
    __syncthreads();
    s0[threadIdx.x]       = psum;
    s0[256 + threadIdx.x] = psq;
    __syncthreads();
    for (int o = 128; o > 0; o >>= 1) {
        if (threadIdx.x < o) {
            s0[threadIdx.x]       += s0[threadIdx.x + o];
            s0[256 + threadIdx.x] += s0[256 + threadIdx.x + o];
        }
        __syncthreads();
    }
    if (threadIdx.x == 0) {
        atomicAdd(&g_bn_sum[c], s0[0]);
        atomicAdd(&g_bn_sq[c],  s0[256]);
    }
}

// ---------------- BN finalize ----------------
__global__ void bn_final_kernel(const float* __restrict__ ascale) {
    int c = threadIdx.x;
    float s = __ldg(ascale + c);
    float m = g_bn_sum[c] * (1.f / (B_*HW_));
    float v = g_bn_sq[c]  * (1.f / (B_*HW_)) - m*m;
    g_bnm[c] = s * m;
    g_bnr[c] = rsqrtf(s*s*v + 1e-5f);
}

// ---------------- sigmoid gate + gather + residual add ----------------
__global__ void gather_update_kernel(float* __restrict__ tokens, int g,
                                     const float* __restrict__ ascale,
                                     const float* __restrict__ bng,
                                     const float* __restrict__ bnb) {
    int n = blockIdx.x * 256 + threadIdx.x;
    int c = blockIdx.y;
    int b = blockIdx.z;
    int cell = g_ci[((size_t)b*NG_ + g)*N_ + n];
    float p = g_plane[((size_t)b*C_ + c)*HW_ + cell];
    float y = p * __ldg(ascale + c);
    float t = (y - g_bnm[c]) * g_bnr[c] * __ldg(bng + c) + __ldg(bnb + c);
    float att = 1.f / (1.f + expf(-t));
    tokens[((size_t)b*C_ + c)*N_ + n] += att * p;
}

// ======================================================================
// ChannelMix, persistent-W design.
// W (256x256 fp32) converted to fp16 and staged ONCE per CTA in SMEM
// ([m][k/2] u32, row stride 132 u32 -> conflict-free A-fragment LDS:
// bank = 4*gid + tig). Each CTA then loops over 64-token tiles with a
// bar-free LDS+HMMA k-loop. Grid 74 x B = 148 CTAs = one wave, 1 CTA/SM.
// cm1: LN -> GEMM1 -> relu -> g_h (token-major fp16)
// cm2: g_h -> GEMM2 -> tokens += (.+b2)*scale
// ======================================================================
#define WH_STRIDE  132
#define TILES_PB   (N_/64)     // 512
#define CM_GRIDX   74
#define CM1_SMEM   ((256*WH_STRIDE + 64*WH_STRIDE + 256 + 256 + 64 + 64 + 256 + 256) * 4)
#define CM2_SMEM   ((256*WH_STRIDE + 64*WH_STRIDE) * 4)

__device__ __forceinline__ void cm_stage_w(const float* __restrict__ Wg,
                                           uint32_t* __restrict__ Wh, int tid) {
    for (int idx = tid; idx < 256*32; idx += 256) {
        int row = idx >> 5;
        int cg  = idx & 31;                    // 8 floats -> 4 u32 halves
        const float4* wp = reinterpret_cast<const float4*>(Wg + (size_t)row*C_ + cg*8);
        float4 u = wp[0], v = wp[1];
        __half2 h0 = __floats2half2_rn(u.x, u.y);
        __half2 h1 = __floats2half2_rn(u.z, u.w);
        __half2 h2 = __floats2half2_rn(v.x, v.y);
        __half2 h3 = __floats2half2_rn(v.z, v.w);
        *reinterpret_cast<uint4*>(Wh + row*WH_STRIDE + cg*4) =
            make_uint4(*(uint32_t*)&h0, *(uint32_t*)&h1, *(uint32_t*)&h2, *(uint32_t*)&h3);
    }
}

__device__ __forceinline__ void cm_gemm_persist(const uint32_t* __restrict__ Xs,
                                                const uint32_t* __restrict__ Wh,
                                                int gid, int tig, int wm, int wn,
                                                float acc[4][4][4]) {
    #pragma unroll
    for (int i = 0; i < 4; i++)
        #pragma unroll
        for (int j = 0; j < 4; j++)
            #pragma unroll
            for (int r = 0; r < 4; r++) acc[i][j][r] = 0.f;

    #pragma unroll 4
    for (int k16 = 0; k16 < 16; k16++) {
        int kb = k16 * 8;
        uint32_t bfr[4][2];
        #pragma unroll
        for (int j = 0; j < 4; j++) {
            const uint32_t* xr = Xs + (wn + j*8 + gid)*WH_STRIDE + kb;
            bfr[j][0] = xr[tig];
            bfr[j][1] = xr[tig + 4];
        }
        #pragma unroll
        for (int i = 0; i < 4; i++) {
            const uint32_t* wr  = Wh + (wm + i*16 + gid)*WH_STRIDE + kb;
            const uint32_t* wr8 = wr + 8*WH_STRIDE;
            uint32_t afr[4];
            afr[0] = wr[tig];
            afr[1] = wr8[tig];
            afr[2] = wr[tig + 4];
            afr[3] = wr8[tig + 4];
            #pragma unroll
            for (int j = 0; j < 4; j++)
                mma_f16(acc[i][j], afr, bfr[j]);
        }
    }
}

__global__ void __launch_bounds__(256, 1)
cm1_kernel(const float* __restrict__ tokens,
           const float* __restrict__ lng, const float* __restrict__ lnb,
           const float* __restrict__ W1,  const float* __restrict__ b1) {
    extern __shared__ uint32_t smu[];
    uint32_t* Wh   = smu;                          // [256][132]
    uint32_t* Xs   = Wh + 256*WH_STRIDE;           // [64][132]
    float* red     = (float*)(Xs + 64*WH_STRIDE);  // [4][64]
    float* red2    = red + 256;
    float* mean_s  = red2 + 256;                   // [64]
    float* rstd_s  = mean_s + 64;
    float* lg      = rstd_s + 64;                  // [256]
    float* lb      = lg + 256;
    __half* Xh     = reinterpret_cast<__half*>(Xs);

    const int tid  = threadIdx.x;
    const int b    = blockIdx.y;
    const int lane = tid & 31;
    const int wid  = tid >> 5;
    const int gid  = lane >> 2;
    const int tig  = lane & 3;
    const int wm   = (wid >> 1) * 64;
    const int wn   = (wid & 1)  * 32;
    const int part = tid >> 6;
    const int nn   = tid & 63;

    cm_stage_w(W1, Wh, tid);
    lg[tid] = lng[tid];
    lb[tid] = lnb[tid];
    __syncthreads();

    for (int tile = blockIdx.x; tile < TILES_PB; tile += CM_GRIDX) {
        const int n0 = tile * 64;
        // ---- LN over channels into Xs (fp16 [n][k]) ----
        const float* tcol = tokens + (size_t)b*C_*N_ + n0 + nn;
        float s = 0.f, ss = 0.f;
        #pragma unroll 8
        for (int c = part*64; c < part*64 + 64; c++) {
            float x = tcol[(size_t)c * N_];
            s += x; ss += x*x;
        }
        red [part*64 + nn] = s;
        red2[part*64 + nn] = ss;
        __syncthreads();
        if (tid < 64) {
            float sm  = red [tid] + red [64+tid] + red [128+tid] + red [192+tid];
            float sm2 = red2[tid] + red2[64+tid] + red2[128+tid] + red2[192+tid];
            float m = sm * (1.f / C_);
            mean_s[tid] = m;
            rstd_s[tid] = rsqrtf(sm2 * (1.f / C_) - m*m + 1e-5f);
        }
        __syncthreads();
        {
            float m = mean_s[nn], r = rstd_s[nn];
            #pragma unroll 8
            for (int c = part*64; c < part*64 + 64; c++) {
                float x = tcol[(size_t)c * N_];
                Xh[nn*(2*WH_STRIDE) + c] = __float2half((x - m) * r * lg[c] + lb[c]);
            }
        }
        __syncthreads();

        // ---- GEMM1 (bar-free) ----
        float acc[4][4][4];
        cm_gemm_persist(Xs, Wh, gid, tig, wm, wn, acc);
        __syncthreads();   // Xs reads done before overwrite

        // ---- relu(h + b1) back into Xs ----
        #pragma unroll
        for (int i = 0; i < 4; i++) {
            int m0 = wm + i*16 + gid;
            float bva = __ldg(b1 + m0);
            float bvb = __ldg(b1 + m0 + 8);
            #pragma unroll
            for (int j = 0; j < 4; j++) {
                int col = wn + j*8 + 2*tig;
                Xh[ col   *(2*WH_STRIDE) + m0    ] = __float2half(fmaxf(acc[i][j][0] + bva, 0.f));
                Xh[(col+1)*(2*WH_STRIDE) + m0    ] = __float2half(fmaxf(acc[i][j][1] + bva, 0.f));
                Xh[ col   *(2*WH_STRIDE) + m0 + 8] = __float2half(fmaxf(acc[i][j][2] + bvb, 0.f));
                Xh[(col+1)*(2*WH_STRIDE) + m0 + 8] = __float2half(fmaxf(acc[i][j][3] + bvb, 0.f));
            }
        }
        __syncthreads();

        // ---- dump h tile to g_h (token-major, coalesced uint4) ----
        for (int idx = tid; idx < 64*32; idx += 256) {
            int rowN = idx >> 5;
            int cg   = idx & 31;
            uint4 v = *reinterpret_cast<uint4*>(Xs + rowN*WH_STRIDE + cg*4);
            *reinterpret_cast<uint4*>(g_h + ((size_t)b*N_ + n0 + rowN)*C_ + cg*8) = v;
        }
        __syncthreads();   // protect Xs before next tile's LN
    }
}

__global__ void __launch_bounds__(256, 1)
cm2_kernel(float* __restrict__ tokens,
           const float* __restrict__ W2, const float* __restrict__ b2,
           const float* __restrict__ csc) {
    extern __shared__ uint32_t smu[];
    uint32_t* Wh = smu;                    // [256][132]
    uint32_t* Xs = Wh + 256*WH_STRIDE;     // [64][132]

    const int tid  = threadIdx.x;
    const int b    = blockIdx.y;
    const int lane = tid & 31;
    const int wid  = tid >> 5;
    const int gid  = lane >> 2;
    const int tig  = lane & 3;
    const int wm   = (wid >> 1) * 64;
    const int wn   = (wid & 1)  * 32;

    cm_stage_w(W2, Wh, tid);
    __syncthreads();

    for (int tile = blockIdx.x; tile < TILES_PB; tile += CM_GRIDX) {
        const int n0 = tile * 64;
        // ---- stage h tile (coalesced) ----
        for (int idx = tid; idx < 64*32; idx += 256) {
            int rowN = idx >> 5;
            int cg   = idx & 31;
            uint4 v = *reinterpret_cast<const uint4*>(g_h + ((size_t)b*N_ + n0 + rowN)*C_ + cg*8);
            *reinterpret_cast<uint4*>(Xs + rowN*WH_STRIDE + cg*4) = v;
        }
        __syncthreads();

        // ---- GEMM2 (bar-free) ----
        float acc[4][4][4];
        cm_gemm_persist(Xs, Wh, gid, tig, wm, wn, acc);

        // ---- tokens += (h2 + b2) * scale ----
        #pragma unroll
        for (int i = 0; i < 4; i++) {
            int m0 = wm + i*16 + gid;
            float b2a = __ldg(b2 + m0),     sca = __ldg(csc + m0);
            float b2b = __ldg(b2 + m0 + 8), scb = __ldg(csc + m0 + 8);
            #pragma unroll
            for (int j = 0; j < 4; j++) {
                int col = wn + j*8 + 2*tig;
                float* p0 = tokens + ((size_t)b*C_ + m0    )*N_ + n0 + col;
                float* p1 = tokens + ((size_t)b*C_ + m0 + 8)*N_ + n0 + col;
                float2 t0 = *reinterpret_cast<float2*>(p0);
                float2 t1 = *reinterpret_cast<float2*>(p1);
                t0.x += (acc[i][j][0] + b2a) * sca;
                t0.y += (acc[i][j][1] + b2a) * sca;
                t1.x += (acc[i][j][2] + b2b) * scb;
                t1.y += (acc[i][j][3] + b2b) * scb;
                *reinterpret_cast<float2*>(p0) = t0;
                *reinterpret_cast<float2*>(p1) = t1;
            }
        }
        __syncthreads();   // Xs reads done before next tile's staging
    }
}

// ---------------- launch ----------------
extern "C" void kernel_launch(void* const* d_in, const int* in_sizes, int n_in,
                              void* d_out, int out_size) {
    const float* tokens_in  = (const float*)d_in[0];
    const int*   cell_ind   = (const int*)  d_in[1];
    const float* occ        = (const float*)d_in[2];
    const float* smix_ln_g  = (const float*)d_in[3];
    const float* smix_ln_b  = (const float*)d_in[4];
    const float* ffn_w1     = (const float*)d_in[5];
    const float* ffn_b1     = (const float*)d_in[6];
    const float* ffn_w2     = (const float*)d_in[7];
    const float* ffn_b2     = (const float*)d_in[8];
    const float* att_scale  = (const float*)d_in[9];
    const float* att_bn_g   = (const float*)d_in[10];
    const float* att_bn_b   = (const float*)d_in[11];
    const float* cmix_ln_g  = (const float*)d_in[12];
    const float* cmix_ln_b  = (const float*)d_in[13];
    const float* cmix_w1    = (const float*)d_in[14];
    const float* cmix_b1    = (const float*)d_in[15];
    const float* cmix_w2    = (const float*)d_in[16];
    const float* cmix_b2    = (const float*)d_in[17];
    const float* cmix_scale = (const float*)d_in[18];
    float* tokens = (float*)d_out;

    cudaFuncSetAttribute(dwconv2_kernel, cudaFuncAttributeMaxDynamicSharedMemorySize, CONV_SMEM);
    cudaFuncSetAttribute(cm1_kernel,     cudaFuncAttributeMaxDynamicSharedMemorySize, CM1_SMEM);
    cudaFuncSetAttribute(cm2_kernel,     cudaFuncAttributeMaxDynamicSharedMemorySize, CM2_SMEM);

    copy4_kernel<<<(B_*C_*N_/4 + 255)/256, 256>>>(
        reinterpret_cast<const float4*>(tokens_in),
        reinterpret_cast<float4*>(tokens), B_*C_*N_/4);

    zero_counts_kernel <<<(B_*NG_*HW_ + 255)/256, 256>>>();
    count_scatter_kernel<<<(B_*NG_*N_ + 255)/256, 256>>>(cell_ind, occ);
    wpt_kernel          <<<(B_*NG_*N_ + 255)/256, 256>>>(occ);

    for (int d = 0; d < DEPTH_; d++) {
        int g = d % NG_;
        grid_init_kernel<<<(B_*C_*HW_/4)/256, 256>>>((d == 3 && g == 0) ? 1 : 0);

        ln_scatter_kernel<<<dim3(N_/256, B_), 256>>>(tokens, smix_ln_g + d*C_, smix_ln_b + d*C_, g);

        dwconv2_kernel<<<B_*C_, 256, CONV_SMEM>>>(ffn_w1 + d*C_*9, ffn_b1 + d*C_,
                                                  ffn_w2 + d*C_*9, ffn_b2 + d*C_,
                                                  (d == 0) ? 1 : 0);

        bn_final_kernel<<<1, C_>>>(att_scale + d*C_);

        gather_update_kernel<<<dim3(N_/256, C_, B_), 256>>>(tokens, g,
                                                            att_scale + d*C_,
                                                            att_bn_g + d*C_,
                                                            att_bn_b + d*C_);

        cm1_kernel<<<dim3(CM_GRIDX, B_), 256, CM1_SMEM>>>(
            tokens, cmix_ln_g + d*C_, cmix_ln_b + d*C_,
            cmix_w1 + d*C_*C_, cmix_b1 + d*C_);

        cm2_kernel<<<dim3(CM_GRIDX, B_), 256, CM2_SMEM>>>(
            tokens, cmix_w2 + d*C_*C_, cmix_b2 + d*C_, cmix_scale + d*C_);
    }
}